// round 9
// baseline (speedup 1.0000x reference)
#include <cuda_runtime.h>
#include <cuda_fp16.h>

// Problem constants
#define BATCH 256
#define NCAPS 1152
#define INC   8
#define KCAPS 10
#define OUTC  16

// u_hat scratch: [K, B, N, OUTC] fp16 = 94.4 MB
__device__ __align__(16) __half g_uhat[(size_t)KCAPS * BATCH * NCAPS * OUTC];

// ---------- packed fp32x2 helpers (sm_103a) ----------
__device__ __forceinline__ unsigned long long pack2(float x, float y) {
    unsigned long long r;
    asm("mov.b64 %0, {%1, %2};" : "=l"(r) : "f"(x), "f"(y));
    return r;
}
__device__ __forceinline__ unsigned long long fma2(unsigned long long a,
                                                   unsigned long long b,
                                                   unsigned long long c) {
    unsigned long long d;
    asm("fma.rn.f32x2 %0, %1, %2, %3;" : "=l"(d) : "l"(a), "l"(b), "l"(c));
    return d;
}
__device__ __forceinline__ unsigned long long add2(unsigned long long a,
                                                   unsigned long long b) {
    unsigned long long d;
    asm("add.rn.f32x2 %0, %1, %2;" : "=l"(d) : "l"(a), "l"(b));
    return d;
}
__device__ __forceinline__ float2 unpack2(unsigned long long v) {
    float2 f;
    asm("mov.b64 {%0, %1}, %2;" : "=f"(f.x), "=f"(f.y) : "l"(v));
    return f;
}
__device__ __forceinline__ unsigned long long h2f2(__half2 h) {
    const float2 f = __half22float2(h);
    return pack2(f.x, f.y);
}

// =====================================================================
// Phase 1: u_hat[k,b,n,o] = sum_i u[b,n,i]*W[k,n,i,o] -> fp16.
// Grid 288 (n-tiles of 4), 320 threads, NO smem: u tile (32KB/CTA) is
// L1-resident, read as coalesced float4 pairs; (u,u) operands built by
// register packs. W in registers (8i x 4o packed f32x2). 3 CTAs/SM.
// =====================================================================
__global__ __launch_bounds__(320, 3)
void uhat_kernel(const float* __restrict__ u, const float* __restrict__ W) {
    const int n0 = blockIdx.x * 4;
    const int tid = threadIdx.x;

    // Thread mapping: 4 oq x 4 nl x 10 k x 2 bsub = 320
    const int oq = tid & 3;            // o quarter
    const int nl = (tid >> 2) & 3;     // n within tile
    int kk = tid >> 4;                 // 0..19
    int bsub = 0;
    if (kk >= KCAPS) { kk -= KCAPS; bsub = 1; }

    const int n = n0 + nl;
    const float* wptr = W + (((kk * NCAPS) + n) * INC) * OUTC + oq * 4;
    unsigned long long wp[8][2];
#pragma unroll
    for (int i = 0; i < 8; i++) {
        const float4 w4 = *reinterpret_cast<const float4*>(wptr + i * OUTC);
        wp[i][0] = pack2(w4.x, w4.y);
        wp[i][1] = pack2(w4.z, w4.w);
    }

    __half* dst_base = g_uhat + (size_t)(kk * BATCH) * NCAPS * OUTC
                              + (size_t)n * OUTC + oq * 4;
    const float* ubase = u + (size_t)n * INC;

#pragma unroll 2
    for (int b = bsub; b < BATCH; b += 2) {
        const float4* up =
            reinterpret_cast<const float4*>(ubase + (size_t)b * (NCAPS * INC));
        const float4 f0 = up[0];   // i = 0..3
        const float4 f1 = up[1];   // i = 4..7
        unsigned long long acc0 = 0ull, acc1 = 0ull;
        acc0 = fma2(pack2(f0.x, f0.x), wp[0][0], acc0);
        acc1 = fma2(pack2(f0.x, f0.x), wp[0][1], acc1);
        acc0 = fma2(pack2(f0.y, f0.y), wp[1][0], acc0);
        acc1 = fma2(pack2(f0.y, f0.y), wp[1][1], acc1);
        acc0 = fma2(pack2(f0.z, f0.z), wp[2][0], acc0);
        acc1 = fma2(pack2(f0.z, f0.z), wp[2][1], acc1);
        acc0 = fma2(pack2(f0.w, f0.w), wp[3][0], acc0);
        acc1 = fma2(pack2(f0.w, f0.w), wp[3][1], acc1);
        acc0 = fma2(pack2(f1.x, f1.x), wp[4][0], acc0);
        acc1 = fma2(pack2(f1.x, f1.x), wp[4][1], acc1);
        acc0 = fma2(pack2(f1.y, f1.y), wp[5][0], acc0);
        acc1 = fma2(pack2(f1.y, f1.y), wp[5][1], acc1);
        acc0 = fma2(pack2(f1.z, f1.z), wp[6][0], acc0);
        acc1 = fma2(pack2(f1.z, f1.z), wp[6][1], acc1);
        acc0 = fma2(pack2(f1.w, f1.w), wp[7][0], acc0);
        acc1 = fma2(pack2(f1.w, f1.w), wp[7][1], acc1);

        const float2 a0 = unpack2(acc0);
        const float2 a1 = unpack2(acc1);
        union { uint2 u32x2; __half2 h[2]; } cv;
        cv.h[0] = __floats2half2_rn(a0.x, a0.y);
        cv.h[1] = __floats2half2_rn(a1.x, a1.y);
        *reinterpret_cast<uint2*>(dst_base + (size_t)b * NCAPS * OUTC) = cv.u32x2;
    }
}

// =====================================================================
// Phase 2: routing for one (k,b) per CTA. 288 threads; u_hat kept in
// registers as __half2 (32 u32 regs/thread), converted to f32x2 on use.
// Accumulation fp32. smem only for reductions (~26 KB). 3 CTAs/SM.
// =====================================================================
#define RT   288
#define RPT  4
#define SPAD 20   // floats per scratch row (16B-aligned, STS.128-friendly)

__global__ __launch_bounds__(RT, 3)
void routing_kernel(float* __restrict__ out) {
    __shared__ __align__(16) float sred[RT * SPAD];   // per-thread s partials
    __shared__ __align__(16) float sB[36 * 16];       // stage-A partials
    __shared__ float swm[9];                          // per-warp max
    __shared__ float swz[9];                          // per-warp Z partial
    __shared__ __align__(16) float sv[16];            // current v_j

    const int tid = threadIdx.x;
    const int lane = tid & 31, warp = tid >> 5;
    const int b = blockIdx.x, k = blockIdx.y;
    const __half* src = g_uhat + ((size_t)(k * BATCH + b)) * NCAPS * OUTC;

    // Load 4 rows x 16 fp16, kept packed as 8 half2 per row
    __half2 uhh[RPT][8];
#pragma unroll
    for (int j = 0; j < RPT; j++) {
        const int n = tid + RT * j;
        const uint4* p = reinterpret_cast<const uint4*>(src + n * OUTC);
        union { uint4 q; __half2 h[4]; } w0, w1;
        w0.q = p[0];
        w1.q = p[1];
#pragma unroll
        for (int c = 0; c < 4; c++) {
            uhh[j][c] = w0.h[c];
            uhh[j][4 + c] = w1.h[c];
        }
    }

    float bl[RPT];
#pragma unroll
    for (int j = 0; j < RPT; j++) bl[j] = 0.f;

    float* myrow = sred + tid * SPAD;

    // ---- iteration 1: uniform coefficients -> s = mean_n u_hat ----
    {
        unsigned long long sp[8];
#pragma unroll
        for (int c = 0; c < 8; c++) sp[c] = h2f2(uhh[0][c]);
#pragma unroll
        for (int j = 1; j < RPT; j++)
#pragma unroll
            for (int c = 0; c < 8; c++) sp[c] = add2(sp[c], h2f2(uhh[j][c]));
#pragma unroll
        for (int c = 0; c < 8; c++)
            reinterpret_cast<unsigned long long*>(myrow)[c] = sp[c];
    }
    __syncthreads();
    {   // stage A: 36 groups x 8 packed cols, each sums 8 scratch rows
        const int o2 = tid & 7, grp = tid >> 3;
        unsigned long long acc = 0ull;
#pragma unroll
        for (int rr = 0; rr < 8; rr++)
            acc = add2(acc, reinterpret_cast<const unsigned long long*>(
                                sred + (grp * 8 + rr) * SPAD)[o2]);
        reinterpret_cast<unsigned long long*>(sB)[grp * 8 + o2] = acc;
    }
    __syncthreads();
    if (tid < 16) {   // stage B + squash
        float s = 0.f;
#pragma unroll
        for (int g = 0; g < 36; g++) s += sB[g * 16 + tid];
        s *= (1.f / (float)NCAPS);
        float q = s * s;
        q += __shfl_xor_sync(0xffffu, q, 8);
        q += __shfl_xor_sync(0xffffu, q, 4);
        q += __shfl_xor_sync(0xffffu, q, 2);
        q += __shfl_xor_sync(0xffffu, q, 1);
        sv[tid] = s * (q / ((1.f + q) * sqrtf(q)));
    }
    __syncthreads();

    // ---- iterations 2 and 3 ----
    for (int it = 0; it < 2; it++) {
        // a[n] = <u_hat[n,:], v>; update logits; warp max
        unsigned long long vp[8];
#pragma unroll
        for (int c = 0; c < 8; c++)
            vp[c] = reinterpret_cast<const unsigned long long*>(sv)[c];
        float mloc = -3.0e38f;
#pragma unroll
        for (int j = 0; j < RPT; j++) {
            unsigned long long ap = 0ull;
#pragma unroll
            for (int c = 0; c < 8; c++) ap = fma2(h2f2(uhh[j][c]), vp[c], ap);
            const float2 af = unpack2(ap);
            bl[j] += af.x + af.y;
            mloc = fmaxf(mloc, bl[j]);
        }
#pragma unroll
        for (int off = 16; off; off >>= 1)
            mloc = fmaxf(mloc, __shfl_xor_sync(0xffffffffu, mloc, off));
        if (lane == 0) swm[warp] = mloc;
        __syncthreads();

        // global max (every thread reads 9 values), exp, warp Z
        float mx = swm[0];
#pragma unroll
        for (int w = 1; w < 9; w++) mx = fmaxf(mx, swm[w]);
        float el[RPT];
        float zloc = 0.f;
#pragma unroll
        for (int j = 0; j < RPT; j++) {
            el[j] = __expf(bl[j] - mx);
            zloc += el[j];
        }
#pragma unroll
        for (int off = 16; off; off >>= 1)
            zloc += __shfl_xor_sync(0xffffffffu, zloc, off);
        if (lane == 0) swz[warp] = zloc;

        // s partials (independent of Z; scale applied in stage B)
        unsigned long long sp[8];
#pragma unroll
        for (int c = 0; c < 8; c++) sp[c] = 0ull;
#pragma unroll
        for (int j = 0; j < RPT; j++) {
            const unsigned long long e2 = pack2(el[j], el[j]);
#pragma unroll
            for (int c = 0; c < 8; c++) sp[c] = fma2(e2, h2f2(uhh[j][c]), sp[c]);
        }
#pragma unroll
        for (int c = 0; c < 8; c++)
            reinterpret_cast<unsigned long long*>(myrow)[c] = sp[c];
        __syncthreads();

        {   // stage A
            const int o2 = tid & 7, grp = tid >> 3;
            unsigned long long acc = 0ull;
#pragma unroll
            for (int rr = 0; rr < 8; rr++)
                acc = add2(acc, reinterpret_cast<const unsigned long long*>(
                                    sred + (grp * 8 + rr) * SPAD)[o2]);
            reinterpret_cast<unsigned long long*>(sB)[grp * 8 + o2] = acc;
        }
        __syncthreads();

        if (tid < 16) {   // stage B: finish Z, s, squash
            float z = swz[0];
#pragma unroll
            for (int w = 1; w < 9; w++) z += swz[w];
            float s = 0.f;
#pragma unroll
            for (int g = 0; g < 36; g++) s += sB[g * 16 + tid];
            s *= (1.f / z);
            float q = s * s;
            q += __shfl_xor_sync(0xffffu, q, 8);
            q += __shfl_xor_sync(0xffffu, q, 4);
            q += __shfl_xor_sync(0xffffu, q, 2);
            q += __shfl_xor_sync(0xffffu, q, 1);
            const float v = s * (q / ((1.f + q) * sqrtf(q)));
            sv[tid] = v;
            if (it == 1)
                out[((size_t)(k * BATCH) + b) * OUTC + tid] = v;
        }
        __syncthreads();
    }
}

extern "C" void kernel_launch(void* const* d_in, const int* in_sizes, int n_in,
                              void* d_out, int out_size) {
    const float* u = (const float*)d_in[0];   // [256, 1152, 8]
    const float* W = (const float*)d_in[1];   // [10, 1152, 8, 16]
    float* out = (float*)d_out;               // [10, 256, 1, 1, 16]

    uhat_kernel<<<NCAPS / 4, 320>>>(u, W);
    routing_kernel<<<dim3(BATCH, KCAPS), RT>>>(out);
}

// round 10
// speedup vs baseline: 1.3465x; 1.3465x over previous
#include <cuda_runtime.h>
#include <cuda_fp16.h>

// Problem constants
#define BATCH 256
#define NCAPS 1152
#define INC   8
#define KCAPS 10
#define OUTC  16
#define KCH   5      // k-chunk size

// u_hat scratch: [K, B, N, OUTC] fp16 = 94.4 MB (each 47MB k-chunk L2-resident
// between its producer launch and consumer launch)
__device__ __align__(16) __half g_uhat[(size_t)KCAPS * BATCH * NCAPS * OUTC];

// ---------- packed fp32x2 helpers (sm_103a) ----------
__device__ __forceinline__ unsigned long long pack2(float x, float y) {
    unsigned long long r;
    asm("mov.b64 %0, {%1, %2};" : "=l"(r) : "f"(x), "f"(y));
    return r;
}
__device__ __forceinline__ unsigned long long fma2(unsigned long long a,
                                                   unsigned long long b,
                                                   unsigned long long c) {
    unsigned long long d;
    asm("fma.rn.f32x2 %0, %1, %2, %3;" : "=l"(d) : "l"(a), "l"(b), "l"(c));
    return d;
}
__device__ __forceinline__ unsigned long long add2(unsigned long long a,
                                                   unsigned long long b) {
    unsigned long long d;
    asm("add.rn.f32x2 %0, %1, %2;" : "=l"(d) : "l"(a), "l"(b));
    return d;
}
__device__ __forceinline__ float2 unpack2(unsigned long long v) {
    float2 f;
    asm("mov.b64 {%0, %1}, %2;" : "=f"(f.x), "=f"(f.y) : "l"(v));
    return f;
}

// =====================================================================
// Phase-1 body: u_hat for one 4-wide n-tile, one k-chunk of 5.
// 320 threads = 4 oq x 4 nl x 5 kk x 4 bsub. W in registers, u staged
// duplicated in (dynamic) smem: [256 b][32 r] float2 = 64 KB.
// =====================================================================
__device__ __forceinline__ void uhat_body(const float* __restrict__ u,
                                          const float* __restrict__ W,
                                          float2* udup, int ntile, int kbase) {
    const int n0 = ntile * 4;
    const int tid = threadIdx.x;

    for (int idx = tid; idx < BATCH * 32; idx += 320) {
        const int b = idx >> 5, r = idx & 31;
        const float v = u[b * (NCAPS * INC) + n0 * INC + r];
        udup[idx] = make_float2(v, v);
    }

    const int oq = tid & 3;
    const int nl = (tid >> 2) & 3;
    const int rest = tid >> 4;           // 0..19
    const int kk = rest % KCH;           // 0..4
    const int bsub = rest / KCH;         // 0..3
    const int k = kbase + kk;
    const int n = n0 + nl;

    const float* wptr = W + (((k * NCAPS) + n) * INC) * OUTC + oq * 4;
    unsigned long long wp[8][2];
#pragma unroll
    for (int i = 0; i < 8; i++) {
        const float4 w4 = *reinterpret_cast<const float4*>(wptr + i * OUTC);
        wp[i][0] = pack2(w4.x, w4.y);
        wp[i][1] = pack2(w4.z, w4.w);
    }
    __syncthreads();

    __half* dst_base = g_uhat + (size_t)(k * BATCH) * NCAPS * OUTC
                              + (size_t)n * OUTC + oq * 4;

#pragma unroll 2
    for (int b = bsub; b < BATCH; b += 4) {
        const ulonglong2* up =
            reinterpret_cast<const ulonglong2*>(udup + b * 32 + nl * 8);
        unsigned long long acc0 = 0ull, acc1 = 0ull;
#pragma unroll
        for (int i2 = 0; i2 < 4; i2++) {
            const ulonglong2 uu = up[i2];
            acc0 = fma2(uu.x, wp[2 * i2][0], acc0);
            acc1 = fma2(uu.x, wp[2 * i2][1], acc1);
            acc0 = fma2(uu.y, wp[2 * i2 + 1][0], acc0);
            acc1 = fma2(uu.y, wp[2 * i2 + 1][1], acc1);
        }
        const float2 a0 = unpack2(acc0);
        const float2 a1 = unpack2(acc1);
        union { uint2 u32x2; __half2 h[2]; } cv;
        cv.h[0] = __floats2half2_rn(a0.x, a0.y);
        cv.h[1] = __floats2half2_rn(a1.x, a1.y);
        *reinterpret_cast<uint2*>(dst_base + (size_t)b * NCAPS * OUTC) = cv.u32x2;
    }
}

// =====================================================================
// Routing body for one (k,b). 288 ACTIVE threads (callers may run 320;
// tid>=288 = whole warp 9 idles through block-level syncs).
// u_hat in registers as packed f32x2 (4 rows x 8). smem via pointer.
// Layout (floats): sred[288*20] | sB[36*16] | sv[16] | swm[9] | swz[9]
// =====================================================================
#define RT    288
#define RPT   4
#define SPAD  20
#define RSM_FLOATS (RT * SPAD + 36 * 16 + 16 + 9 + 9)

__device__ __forceinline__ void routing_body(float* __restrict__ out,
                                             float* sm, int k, int b) {
    float* sred = sm;
    float* sB   = sred + RT * SPAD;
    float* sv   = sB + 36 * 16;
    float* swm  = sv + 16;
    float* swz  = swm + 9;

    const int tid = threadIdx.x;
    const int lane = tid & 31, warp = tid >> 5;
    const bool act = (tid < RT);
    const __half* src = g_uhat + ((size_t)(k * BATCH + b)) * NCAPS * OUTC;

    unsigned long long uh[RPT][8];
    float bl[RPT];
    float* myrow = sred + tid * SPAD;

    if (act) {
#pragma unroll
        for (int j = 0; j < RPT; j++) {
            const int n = tid + RT * j;
            const uint4* p = reinterpret_cast<const uint4*>(src + n * OUTC);
            union { uint4 q; __half2 h[4]; } w0, w1;
            w0.q = p[0];
            w1.q = p[1];
#pragma unroll
            for (int c = 0; c < 4; c++) {
                const float2 f0 = __half22float2(w0.h[c]);
                uh[j][c] = pack2(f0.x, f0.y);
                const float2 f1 = __half22float2(w1.h[c]);
                uh[j][4 + c] = pack2(f1.x, f1.y);
            }
        }
#pragma unroll
        for (int j = 0; j < RPT; j++) bl[j] = 0.f;

        // ---- iteration 1 partial: s = mean_n u_hat ----
        unsigned long long sp[8];
#pragma unroll
        for (int c = 0; c < 8; c++) sp[c] = uh[0][c];
#pragma unroll
        for (int j = 1; j < RPT; j++)
#pragma unroll
            for (int c = 0; c < 8; c++) sp[c] = add2(sp[c], uh[j][c]);
#pragma unroll
        for (int c = 0; c < 8; c++)
            reinterpret_cast<unsigned long long*>(myrow)[c] = sp[c];
    }
    __syncthreads();
    if (act) {   // stage A: 36 groups x 8 packed cols, each sums 8 rows
        const int o2 = tid & 7, grp = tid >> 3;
        unsigned long long acc = 0ull;
#pragma unroll
        for (int rr = 0; rr < 8; rr++)
            acc = add2(acc, reinterpret_cast<const unsigned long long*>(
                                sred + (grp * 8 + rr) * SPAD)[o2]);
        reinterpret_cast<unsigned long long*>(sB)[grp * 8 + o2] = acc;
    }
    __syncthreads();
    if (tid < 16) {   // stage B + squash
        float s = 0.f;
#pragma unroll
        for (int g = 0; g < 36; g++) s += sB[g * 16 + tid];
        s *= (1.f / (float)NCAPS);
        float q = s * s;
        q += __shfl_xor_sync(0xffffu, q, 8);
        q += __shfl_xor_sync(0xffffu, q, 4);
        q += __shfl_xor_sync(0xffffu, q, 2);
        q += __shfl_xor_sync(0xffffu, q, 1);
        sv[tid] = s * (q / ((1.f + q) * sqrtf(q)));
    }
    __syncthreads();

    // ---- iterations 2 and 3 ----
    for (int it = 0; it < 2; it++) {
        if (act) {
            unsigned long long vp[8];
#pragma unroll
            for (int c = 0; c < 8; c++)
                vp[c] = reinterpret_cast<const unsigned long long*>(sv)[c];
            float mloc = -3.0e38f;
#pragma unroll
            for (int j = 0; j < RPT; j++) {
                unsigned long long ap = 0ull;
#pragma unroll
                for (int c = 0; c < 8; c++) ap = fma2(uh[j][c], vp[c], ap);
                const float2 af = unpack2(ap);
                bl[j] += af.x + af.y;
                mloc = fmaxf(mloc, bl[j]);
            }
#pragma unroll
            for (int off = 16; off; off >>= 1)
                mloc = fmaxf(mloc, __shfl_xor_sync(0xffffffffu, mloc, off));
            if (lane == 0) swm[warp] = mloc;
        }
        __syncthreads();

        if (act) {
            float mx = swm[0];
#pragma unroll
            for (int w = 1; w < 9; w++) mx = fmaxf(mx, swm[w]);
            float el[RPT];
            float zloc = 0.f;
#pragma unroll
            for (int j = 0; j < RPT; j++) {
                el[j] = __expf(bl[j] - mx);
                zloc += el[j];
            }
#pragma unroll
            for (int off = 16; off; off >>= 1)
                zloc += __shfl_xor_sync(0xffffffffu, zloc, off);
            if (lane == 0) swz[warp] = zloc;

            unsigned long long sp[8];
#pragma unroll
            for (int c = 0; c < 8; c++) sp[c] = 0ull;
#pragma unroll
            for (int j = 0; j < RPT; j++) {
                const unsigned long long e2 = pack2(el[j], el[j]);
#pragma unroll
                for (int c = 0; c < 8; c++) sp[c] = fma2(e2, uh[j][c], sp[c]);
            }
#pragma unroll
            for (int c = 0; c < 8; c++)
                reinterpret_cast<unsigned long long*>(myrow)[c] = sp[c];
        }
        __syncthreads();

        if (act) {   // stage A
            const int o2 = tid & 7, grp = tid >> 3;
            unsigned long long acc = 0ull;
#pragma unroll
            for (int rr = 0; rr < 8; rr++)
                acc = add2(acc, reinterpret_cast<const unsigned long long*>(
                                    sred + (grp * 8 + rr) * SPAD)[o2]);
            reinterpret_cast<unsigned long long*>(sB)[grp * 8 + o2] = acc;
        }
        __syncthreads();

        if (tid < 16) {   // stage B: finish Z, s, squash
            float z = swz[0];
#pragma unroll
            for (int w = 1; w < 9; w++) z += swz[w];
            float s = 0.f;
#pragma unroll
            for (int g = 0; g < 36; g++) s += sB[g * 16 + tid];
            s *= (1.f / z);
            float q = s * s;
            q += __shfl_xor_sync(0xffffu, q, 8);
            q += __shfl_xor_sync(0xffffu, q, 4);
            q += __shfl_xor_sync(0xffffu, q, 2);
            q += __shfl_xor_sync(0xffffu, q, 1);
            const float v = s * (q / ((1.f + q) * sqrtf(q)));
            sv[tid] = v;
            if (it == 1)
                out[((size_t)(k * BATCH) + b) * OUTC + tid] = v;
        }
        __syncthreads();
    }
}

// =====================================================================
// Kernels
// =====================================================================

// Launch 1: u_hat chunk 0 (k 0..4)
__global__ __launch_bounds__(320)
void uhat_kernel(const float* __restrict__ u, const float* __restrict__ W,
                 int kbase) {
    extern __shared__ float2 udup[];
    uhat_body(u, W, udup, blockIdx.x, kbase);
}

// Launch 2 (fused): bid<288 -> u_hat chunk 1 (k 5..9);
//                   bid>=288 -> routing chunk 0 (k 0..4), reads L2-hot u_hat.
__global__ __launch_bounds__(320, 2)
void fused_kernel(const float* __restrict__ u, const float* __restrict__ W,
                  float* __restrict__ out) {
    extern __shared__ char dyn[];
    const int bid = blockIdx.x;
    if (bid < 288) {
        uhat_body(u, W, reinterpret_cast<float2*>(dyn), bid, KCH);
    } else {
        const int rbid = bid - 288;
        routing_body(out, reinterpret_cast<float*>(dyn),
                     rbid >> 8, rbid & 255);
    }
}

// Launch 3: routing chunk 1 (k 5..9), reads L2-hot u_hat.
__global__ __launch_bounds__(RT, 2)
void routing_kernel(float* __restrict__ out) {
    extern __shared__ float dynr[];
    routing_body(out, dynr, KCH + blockIdx.y, blockIdx.x);
}

extern "C" void kernel_launch(void* const* d_in, const int* in_sizes, int n_in,
                              void* d_out, int out_size) {
    const float* u = (const float*)d_in[0];   // [256, 1152, 8]
    const float* W = (const float*)d_in[1];   // [10, 1152, 8, 16]
    float* out = (float*)d_out;               // [10, 256, 1, 1, 16]

    const int smemU = BATCH * 32 * sizeof(float2);     // 65536 B
    const int smemR = RSM_FLOATS * sizeof(float);      // ~25.6 KB
    cudaFuncSetAttribute(uhat_kernel,
                         cudaFuncAttributeMaxDynamicSharedMemorySize, smemU);
    cudaFuncSetAttribute(fused_kernel,
                         cudaFuncAttributeMaxDynamicSharedMemorySize, smemU);
    cudaFuncSetAttribute(routing_kernel,
                         cudaFuncAttributeMaxDynamicSharedMemorySize, smemR);

    // 1) produce chunk 0
    uhat_kernel<<<NCAPS / 4, 320, smemU>>>(u, W, 0);
    // 2) produce chunk 1 + route chunk 0 (co-resident, complementary pipes)
    fused_kernel<<<288 + BATCH * KCH, 320, smemU>>>(u, W, out);
    // 3) route chunk 1
    routing_kernel<<<dim3(BATCH, KCH), RT, smemR>>>(out);
}